// round 7
// baseline (speedup 1.0000x reference)
#include <cuda_runtime.h>
#include <cstdint>

// Problem constants (dataset-fixed: IN=(32,3,512,512), OUT=256, scale=0.5)
#define BC      96
#define IN_HW   512
#define OUT_HW  256
#define TOH     16            // oh rows per block (two 8-row halves)
#define RPH     8             // rows per half
#define MAX_T   12
#define HALFP   260           // odd-column region offset, in 8-byte units
#define MIDW    520           // mid2 row length in 8-byte units

typedef unsigned long long ull;

__device__ __forceinline__ ull pack2(float x, float y) {
    ull r; asm("mov.b64 %0, {%1, %2};" : "=l"(r) : "f"(x), "f"(y)); return r;
}
__device__ __forceinline__ void unpack2(ull v, float& x, float& y) {
    asm("mov.b64 {%0, %1}, %2;" : "=f"(x), "=f"(y) : "l"(v));
}
__device__ __forceinline__ void ffma2(ull& a, ull w, ull v) {
    asm("fma.rn.f32x2 %0, %1, %2, %0;" : "+l"(a) : "l"(w), "l"(v));
}
__device__ __forceinline__ ull fadd2(ull a, ull b) {
    ull r; asm("add.rn.f32x2 %0, %1, %2;" : "=l"(r) : "l"(a), "l"(b)); return r;
}

// even/odd split position (8-byte units): fixed-tap gathers become stride-1.
__device__ __forceinline__ int pos_of(int w) { return (w >> 1) + (w & 1) * HALFP; }

// mirror boundary fold matching the reference table construction
__device__ __forceinline__ int mirr(int w) {
    if (w < 0)   w = -1 - w;
    if (w > IN_HW - 1) w = 2 * IN_HW - 1 - w;
    return w;
}

// ---------------------------------------------------------------------------
// Fused bicubic downsample. Block = 512 threads = one plane x 16 oh x full W.
// FAST PATH (validated per block): weights are position-independent (true for
// this resizer: match-fov is constant), fov = 2o + t + C with mirror folds.
//   Phase 1 (H): circular register window, register weights, FFMA2.
//   Phase 2 (W): analytic mirror positions, register weights, FFMA2.
// Generic table-driven fallback otherwise (H-edge tiles).
// ---------------------------------------------------------------------------
template<int TAPS>
__global__ __launch_bounds__(512, 3) void resize_fused(
    const ull*   __restrict__ in,     // (BC, IN_HW, 256) column pairs
    const float* __restrict__ wh, const int* __restrict__ fh,   // H tables
    const float* __restrict__ ww, const int* __restrict__ fw,   // W tables
    float*       __restrict__ out)    // (BC, OUT_HW, OUT_HW)
{
    __shared__ ull   mid2[TOH / 2][MIDW];     // packed row pairs, split layout
    __shared__ float hw_s[TAPS][TOH];         // per-(t,r) H weights (generic)
    __shared__ int   hf_s[TAPS][TOH];         // per-(t,r) H indices (generic)
    __shared__ float whu[TAPS];               // uniform H weights
    __shared__ float wwu[TAPS];               // uniform W weights
    __shared__ int   wcb_s;                   // W fov affine constant C

    const int tid   = threadIdx.x;            // 0..511
    const int col   = tid & 255;              // owns input cols (2c, 2c+1)
    const int r0    = (tid >> 8) * RPH;       // first oh row of this half
    const int oh0   = blockIdx.x * TOH;
    const int plane = blockIdx.y;

    if (tid < TAPS * TOH) {
        const int t = tid / TOH, r = tid % TOH;
        hw_s[t][r] = wh[t * OUT_HW + oh0 + r];
        hf_s[t][r] = fh[t * OUT_HW + oh0 + r];
    }
    if (tid < TAPS) {                         // uniform candidates (interior o)
        whu[tid] = wh[tid * OUT_HW + 128];
        wwu[tid] = ww[tid * OUT_HW + 128];
    }
    if (tid == 0) wcb_s = fw[128] - 256;      // C  (fov = 2o + t + C at t=0)
    __syncthreads();

    const int C = wcb_s;

    // ---- Validate the analytic structure for this block ----
    bool okp = true;
    if (tid < TAPS * TOH) {                   // H: linear fov + uniform weights
        const int t = tid / TOH, r = tid % TOH;
        okp = (hf_s[t][r] == hf_s[0][0] + 2 * r + t) && (hw_s[t][r] == whu[t]);
    }
    {                                         // W: mirror-affine fov + uniform w
        #pragma unroll
        for (int t = 0; t < TAPS; ++t) {
            okp = okp && (fw[t * OUT_HW + col] == mirr(2 * col + t + C))
                      && (ww[t * OUT_HW + col] == wwu[t]);
        }
    }
    const int fast = __syncthreads_and(okp);

    const ull* base = in + (size_t)plane * IN_HW * 256 + col;

    if (fast) {
        // -------- Phase 1: circular register window, register weights -----
        ull hwr[TAPS];
        #pragma unroll
        for (int t = 0; t < TAPS; ++t) hwr[t] = pack2(whu[t], whu[t]);

        ull v[TAPS];
        const int b0 = hf_s[0][0] + 2 * r0;
        #pragma unroll
        for (int t = 0; t < TAPS; ++t)
            v[t] = base[(size_t)(b0 + t) * 256];

        ull stash = 0;
        #pragma unroll
        for (int j = 0; j < RPH; ++j) {
            ull a0 = 0, a1 = 0;
            ffma2(a0, hwr[0], v[(2 * j)     % TAPS]);
            ffma2(a1, hwr[1], v[(2 * j + 1) % TAPS]);
            if (j < RPH - 1) {                // refill the two consumed slots
                v[(2 * j)     % TAPS] = base[(size_t)(b0 + 2 * j + TAPS)     * 256];
                v[(2 * j + 1) % TAPS] = base[(size_t)(b0 + 2 * j + TAPS + 1) * 256];
            }
            #pragma unroll
            for (int t = 2; t < TAPS; ++t) {
                if (t & 1) ffma2(a1, hwr[t], v[(2 * j + t) % TAPS]);
                else       ffma2(a0, hwr[t], v[(2 * j + t) % TAPS]);
            }
            const ull acc = fadd2(a0, a1);    // (evenColVal, oddColVal)
            if ((j & 1) == 0) stash = acc;
            else {                            // repack across the row pair
                float ex, ey, ox, oy;
                unpack2(stash, ex, ey);
                unpack2(acc,   ox, oy);
                const int rp = (r0 >> 1) + (j >> 1);
                mid2[rp][col]         = pack2(ex, ox);
                mid2[rp][col + HALFP] = pack2(ey, oy);
            }
        }
        __syncthreads();

        // -------- Phase 2: analytic positions, register weights -----------
        ull pwr[TAPS];
        int pr[TAPS];
        #pragma unroll
        for (int t = 0; t < TAPS; ++t) {
            pwr[t] = pack2(wwu[t], wwu[t]);
            pr[t]  = pos_of(mirr(2 * col + t + C));
        }

        float* ob = out + ((size_t)plane * OUT_HW + oh0 + r0) * OUT_HW + col;
        #pragma unroll
        for (int p = 0; p < RPH / 2; ++p) {
            const int rp = (r0 >> 1) + p;
            ull a0 = 0, a1 = 0;
            #pragma unroll
            for (int t = 0; t < TAPS; ++t) {
                if (t & 1) ffma2(a1, pwr[t], mid2[rp][pr[t]]);
                else       ffma2(a0, pwr[t], mid2[rp][pr[t]]);
            }
            float x, y; unpack2(fadd2(a0, a1), x, y);
            ob[(size_t)(2 * p)     * OUT_HW] = x;
            ob[(size_t)(2 * p + 1) * OUT_HW] = y;
        }
    } else {
        // -------- Generic table-driven path (H-edge tiles) ----------------
        float wr[TAPS]; int pr[TAPS];
        #pragma unroll
        for (int t = 0; t < TAPS; ++t) {
            wr[t] = ww[t * OUT_HW + col];
            pr[t] = pos_of(fw[t * OUT_HW + col]);
        }

        float sx = 0.f, sy = 0.f;
        #pragma unroll
        for (int j = 0; j < RPH; ++j) {
            const int r = r0 + j;
            float ax = 0.f, ay = 0.f;
            #pragma unroll
            for (int t = 0; t < TAPS; ++t) {
                float x, y; unpack2(base[(size_t)hf_s[t][r] * 256], x, y);
                ax = fmaf(hw_s[t][r], x, ax);
                ay = fmaf(hw_s[t][r], y, ay);
            }
            if ((j & 1) == 0) { sx = ax; sy = ay; }
            else {
                const int rp = (r0 >> 1) + (j >> 1);
                mid2[rp][col]         = pack2(sx, ax);
                mid2[rp][col + HALFP] = pack2(sy, ay);
            }
        }
        __syncthreads();

        float* ob = out + ((size_t)plane * OUT_HW + oh0 + r0) * OUT_HW + col;
        #pragma unroll
        for (int p = 0; p < RPH / 2; ++p) {
            const int rp = (r0 >> 1) + p;
            float ax = 0.f, ay = 0.f;
            #pragma unroll
            for (int t = 0; t < TAPS; ++t) {
                float x, y; unpack2(mid2[rp][pr[t]], x, y);
                ax = fmaf(wr[t], x, ax);
                ay = fmaf(wr[t], y, ay);
            }
            ob[(size_t)(2 * p)     * OUT_HW] = ax;
            ob[(size_t)(2 * p + 1) * OUT_HW] = ay;
        }
    }
}

// ---------------------------------------------------------------------------
// Generic-taps fallback (any taps; table path everywhere).
// ---------------------------------------------------------------------------
__global__ __launch_bounds__(512) void resize_fused_generic(
    const ull*   __restrict__ in,
    const float* __restrict__ wh, const int* __restrict__ fh,
    const float* __restrict__ ww, const int* __restrict__ fw,
    float*       __restrict__ out, int taps)
{
    __shared__ ull   mid2[TOH / 2][MIDW];
    __shared__ float hw_s[MAX_T][TOH];
    __shared__ int   hf_s[MAX_T][TOH];

    const int tid   = threadIdx.x;
    const int col   = tid & 255;
    const int r0    = (tid >> 8) * RPH;
    const int oh0   = blockIdx.x * TOH;
    const int plane = blockIdx.y;

    if (tid < taps * TOH) {
        const int t = tid / TOH, r = tid % TOH;
        hw_s[t][r] = wh[t * OUT_HW + oh0 + r];
        hf_s[t][r] = fh[t * OUT_HW + oh0 + r];
    }
    float wr[MAX_T]; int pr[MAX_T];
    #pragma unroll
    for (int t = 0; t < MAX_T; ++t) {
        if (t < taps) {
            wr[t] = ww[t * OUT_HW + col];
            pr[t] = pos_of(fw[t * OUT_HW + col]);
        } else { wr[t] = 0.f; pr[t] = 0; }
    }
    __syncthreads();

    const ull* base = in + (size_t)plane * IN_HW * 256 + col;
    float sx = 0.f, sy = 0.f;
    for (int j = 0; j < RPH; ++j) {
        const int r = r0 + j;
        float ax = 0.f, ay = 0.f;
        #pragma unroll
        for (int t = 0; t < MAX_T; ++t) {
            if (t < taps) {
                float x, y; unpack2(base[(size_t)hf_s[t][r] * 256], x, y);
                ax = fmaf(hw_s[t][r], x, ax);
                ay = fmaf(hw_s[t][r], y, ay);
            }
        }
        if ((j & 1) == 0) { sx = ax; sy = ay; }
        else {
            const int rp = (r0 >> 1) + (j >> 1);
            mid2[rp][col]         = pack2(sx, ax);
            mid2[rp][col + HALFP] = pack2(sy, ay);
        }
    }
    __syncthreads();

    float* ob = out + ((size_t)plane * OUT_HW + oh0 + r0) * OUT_HW + col;
    for (int p = 0; p < RPH / 2; ++p) {
        const int rp = (r0 >> 1) + p;
        float ax = 0.f, ay = 0.f;
        #pragma unroll
        for (int t = 0; t < MAX_T; ++t) {
            if (t < taps) {
                float x, y; unpack2(mid2[rp][pr[t]], x, y);
                ax = fmaf(wr[t], x, ax);
                ay = fmaf(wr[t], y, ay);
            }
        }
        ob[(size_t)(2 * p)     * OUT_HW] = ax;
        ob[(size_t)(2 * p + 1) * OUT_HW] = ay;
    }
}

// ---------------------------------------------------------------------------
// Inputs (metadata order): in_tensor, w2, fov2 (H axis), w3, fov3 (W axis)
// ---------------------------------------------------------------------------
extern "C" void kernel_launch(void* const* d_in, const int* in_sizes, int n_in,
                              void* d_out, int out_size)
{
    const ull*   in   = (const ull*)  d_in[0];
    const float* w2   = (const float*)d_in[1];
    const int*   fov2 = (const int*)  d_in[2];
    const float* w3   = (const float*)d_in[3];
    const int*   fov3 = (const int*)  d_in[4];
    float* out = (float*)d_out;

    const int taps = in_sizes[1] / OUT_HW;
    dim3 grid(OUT_HW / TOH, BC);                  // (16, 96) = 1536 blocks

    switch (taps) {
    case 6:  resize_fused<6> <<<grid, 512>>>(in, w2, fov2, w3, fov3, out); break;
    case 7:  resize_fused<7> <<<grid, 512>>>(in, w2, fov2, w3, fov3, out); break;
    case 8:  resize_fused<8> <<<grid, 512>>>(in, w2, fov2, w3, fov3, out); break;
    case 9:  resize_fused<9> <<<grid, 512>>>(in, w2, fov2, w3, fov3, out); break;
    case 10: resize_fused<10><<<grid, 512>>>(in, w2, fov2, w3, fov3, out); break;
    case 11: resize_fused<11><<<grid, 512>>>(in, w2, fov2, w3, fov3, out); break;
    case 12: resize_fused<12><<<grid, 512>>>(in, w2, fov2, w3, fov3, out); break;
    default: resize_fused_generic<<<grid, 512>>>(in, w2, fov2, w3, fov3, out, taps); break;
    }
}